// round 14
// baseline (speedup 1.0000x reference)
#include <cuda_runtime.h>
#include <cuda_bf16.h>
#include <math.h>
#include <stdint.h>

#define MAXN 2744
#define AEVD 1008
#define NS 7
#define MAXTILES 56

// ---------------- scratch (static device globals) ----------------
__device__ float g_aev [(size_t)MAXN * AEVD];
__device__ float g_gaev[(size_t)MAXN * AEVD];
__device__ float g_h1[(size_t)8 * MAXN * 256];
__device__ float g_h2[(size_t)8 * MAXN * 192];
__device__ float g_g1[(size_t)8 * MAXN * 256];
__device__ float g_g2[(size_t)8 * MAXN * 192];
__device__ float g_g3[(size_t)8 * MAXN * 160];
__device__ float g_grad[MAXN * 3];
__device__ float g_energy;
__device__ int   g_cnt[NS];
__device__ int   g_list[NS * MAXN];
__device__ int   g_tilecnt;
__device__ int   g_tile_s[MAXTILES];
__device__ int   g_tile_r[MAXTILES];

#define PI_F 3.14159265358979323846f

__device__ __forceinline__ float celu01(float x) {
    return x > 0.f ? x : 0.1f * expm1f(10.f * x);
}
__device__ __forceinline__ float dcelu_y(float y) {
    return y > 0.f ? 1.f : fmaf(y, 10.f, 1.f);
}
__device__ __forceinline__ float fcut(float d, float rc) {
    return d < rc ? 0.5f * cosf(PI_F * d / rc) + 0.5f : 0.f;
}
__device__ __forceinline__ float dfcut(float d, float rc) {
    return d < rc ? -0.5f * (PI_F / rc) * sinf(PI_F * d / rc) : 0.f;
}
__device__ __forceinline__ int pair_index(int sa, int sb) {
    int lo = min(sa, sb), hi = max(sa, sb);
    return lo * NS - (lo * (lo - 1)) / 2 + (hi - lo);
}

// ---- bf16 split helpers ----
__device__ __forceinline__ uint2 splitpack2(float2 v) {
    __nv_bfloat162 h = __float22bfloat162_rn(v);
    float r0 = v.x - __low2float(h);
    float r1 = v.y - __high2float(h);
    __nv_bfloat162 l = __float22bfloat162_rn(make_float2(r0, r1));
    uint2 o;
    o.x = *reinterpret_cast<unsigned int*>(&h);
    o.y = *reinterpret_cast<unsigned int*>(&l);
    return o;
}
__device__ __forceinline__ void mma_bf16(float c[4], uint32_t a0, uint32_t a1,
                                         uint32_t a2, uint32_t a3,
                                         uint32_t b0, uint32_t b1) {
    asm("mma.sync.aligned.m16n8k16.row.col.f32.bf16.bf16.f32 "
        "{%0,%1,%2,%3}, {%4,%5,%6,%7}, {%8,%9}, {%0,%1,%2,%3};"
        : "+f"(c[0]), "+f"(c[1]), "+f"(c[2]), "+f"(c[3])
        : "r"(a0), "r"(a1), "r"(a2), "r"(a3), "r"(b0), "r"(b1));
}

// ---------------- init (g_gaev NOT zeroed; ghost rows guarded in bwd) ----------------
__global__ void k_zero(int N) {
    size_t na = (size_t)N * AEVD;
    size_t total = na + (size_t)3 * N;
    for (size_t i = (size_t)blockIdx.x * blockDim.x + threadIdx.x; i < total;
         i += (size_t)gridDim.x * blockDim.x) {
        if (i < na) g_aev[i] = 0.f;
        else        g_grad[i - na] = 0.f;
    }
    if (blockIdx.x == 0 && threadIdx.x < NS) g_cnt[threadIdx.x] = 0;
    if (blockIdx.x == 0 && threadIdx.x == 0) g_energy = 0.f;
}

// build species lists; fold SAE + ensemble-mean b4 into energy
__global__ void k_build(const int* __restrict__ sgp, const float* __restrict__ sae,
                        const float* __restrict__ b4, int N) {
    int i = blockIdx.x * blockDim.x + threadIdx.x;
    if (i >= N) return;
    int s = sgp[i];
    if (s >= 0) {
        int p = atomicAdd(&g_cnt[s], 1);
        g_list[s * MAXN + p] = i;
        float bsum = 0.f;
#pragma unroll
        for (int m = 0; m < 8; m++) bsum += b4[m * NS + s];
        atomicAdd(&g_energy, sae[s] + 0.125f * bsum);
    }
}

__global__ void k_scan() {
    if (threadIdx.x != 0) return;
    int t = 0;
    for (int s = 0; s < NS; s++) {
        int c = g_cnt[s];
        for (int r0 = 0; r0 < c && t < MAXTILES; r0 += 64) {
            g_tile_s[t] = s;
            g_tile_r[t] = r0;
            t++;
        }
    }
    g_tilecnt = t;
}

// ---------------- merged AEV forward ----------------
__global__ void k_aev_fwd(const float* __restrict__ crd, const int* __restrict__ sp,
                          const int* __restrict__ idx, int P,
                          const int* __restrict__ tri, int T, int nbr) {
    if (blockIdx.x < nbr) {
        int p = blockIdx.x * 128 + threadIdx.x;
        if (p >= P) return;
        int i = idx[p], j = idx[P + p];
        float dx = crd[3 * j + 0] - crd[3 * i + 0];
        float dy = crd[3 * j + 1] - crd[3 * i + 1];
        float dz = crd[3 * j + 2] - crd[3 * i + 2];
        float dist = sqrtf(dx * dx + dy * dy + dz * dz);
        float fc = fcut(dist, 5.2f);
        float* ai = g_aev + (size_t)i * AEVD + sp[j] * 16;
        float* aj = g_aev + (size_t)j * AEVD + sp[i] * 16;
#pragma unroll
        for (int k = 0; k < 16; k++) {
            float mu = 0.8f + 0.275f * (float)k;
            float dm = dist - mu;
            float r = 0.25f * expf(-19.7f * dm * dm) * fc;
            atomicAdd(ai + k, r);
            atomicAdd(aj + k, r);
        }
    } else {
        int t = (blockIdx.x - nbr) * 128 + threadIdx.x;
        if (t >= T) return;
        int c = tri[t], a = tri[T + t], b = tri[2 * T + t];
        float v1x = crd[3 * a + 0] - crd[3 * c + 0];
        float v1y = crd[3 * a + 1] - crd[3 * c + 1];
        float v1z = crd[3 * a + 2] - crd[3 * c + 2];
        float v2x = crd[3 * b + 0] - crd[3 * c + 0];
        float v2y = crd[3 * b + 1] - crd[3 * c + 1];
        float v2z = crd[3 * b + 2] - crd[3 * c + 2];
        float d1 = sqrtf(v1x * v1x + v1y * v1y + v1z * v1z);
        float d2 = sqrtf(v2x * v2x + v2y * v2y + v2z * v2z);
        float dot = v1x * v2x + v1y * v2y + v1z * v2z;
        float cosang = 0.95f * dot / (d1 * d2);
        float ang = acosf(cosang);
        float fcj = fcut(d1, 3.5f) * fcut(d2, 3.5f);
        float u = 0.5f * (d1 + d2);
        float f1[4];
#pragma unroll
        for (int z = 0; z < 4; z++) {
            float th = ang - ((float)z + 0.5f) * (PI_F / 4.f);
            float tt = 0.5f * (1.f + cosf(th));
            f1[z] = powf(tt, 14.1f);
        }
        float f2[8];
#pragma unroll
        for (int s8 = 0; s8 < 8; s8++) {
            float dd = u - (0.8f + 0.3375f * (float)s8);
            f2[s8] = expf(-12.5f * dd * dd);
        }
        int pidx = pair_index(sp[a], sp[b]);
        float* dst = g_aev + (size_t)c * AEVD + 112 + pidx * 32;
#pragma unroll
        for (int s8 = 0; s8 < 8; s8++)
#pragma unroll
            for (int z = 0; z < 4; z++)
                atomicAdd(dst + s8 * 4 + z, 2.f * f2[s8] * f1[z] * fcj);
    }
}

// ---------------- bf16-split (3-term) m16n8k16 GEMM, BK=32 chunks ----------------
// EPI: 1 = celu(x+bias) -> C ; 2 = x*dcelu(H) -> C ; 0 = plain SUMM ; 3 = fused L3+head
template <int KD, int ND, int EPI, bool TB, bool AENS, bool SUMM>
__global__ __launch_bounds__(256) void k_gemm(const float* __restrict__ A,
                                              const float* __restrict__ W,
                                              const float* __restrict__ bias,
                                              const float* __restrict__ H,
                                              float* __restrict__ C,
                                              const float* __restrict__ W4e) {
    const int BM = 64, BN = 64;
    const int KT = (KD + 31) / 32;       // 32-k chunks per ensemble
    const int NT = (SUMM ? 8 : 1) * KT;
    int ti = blockIdx.y;
    if (ti >= g_tilecnt) return;
    int s = g_tile_s[ti];
    int row0 = g_tile_r[ti];
    int m0 = SUMM ? 0 : blockIdx.z;
    int count = g_cnt[s];
    int col0 = blockIdx.x * BN;

    __shared__ uint2 As2[2][16][BM + 4];
    __shared__ uint2 Bs2[2][16][BN + 4];
    __shared__ int rows[BM];
    __shared__ float ered[256];   // EPI==3 energy reduction

    int tid = threadIdx.x;
    if (tid < BM) {
        int r = row0 + tid;
        rows[tid] = (r < count) ? g_list[s * MAXN + r] : -1;
    }
    __syncthreads();

    int kw = tid & 15, rr = tid >> 4;    // A / TB-B loader: 16 k-words x 16 rows (x4)
    int nn = tid & 63, kq = tid >> 6;    // !TB B loader: 64 cols x 4 k-words (x4)

    int arow[4];
#pragma unroll
    for (int i = 0; i < 4; i++) arow[i] = rows[rr + i * 16];

    float2 ra[4], rb[4];

    auto loadT = [&](int t) {
        int m  = SUMM ? (t / KT) : m0;
        int k0 = (SUMM ? (t % KT) : t) * 32;
        const float* Wb = W + (size_t)(m * NS + s) * KD * ND;
        const float* Ab = A + (AENS ? (size_t)m * MAXN * KD : (size_t)0);
        bool kv = (k0 + 2 * kw) < KD;    // guard for partial last chunk (KD=1008)
#pragma unroll
        for (int i = 0; i < 4; i++)
            ra[i] = (kv && arow[i] >= 0)
                ? *(const float2*)&Ab[(size_t)arow[i] * KD + k0 + 2 * kw]
                : make_float2(0.f, 0.f);
        if (!TB) {
#pragma unroll
            for (int i = 0; i < 4; i++) {
                int w = kq + i * 4;
                int nidx = col0 + nn;
                float x = 0.f, y = 0.f;
                if (nidx < ND && (k0 + 2 * w) < KD) {
                    x = Wb[(size_t)(k0 + 2 * w) * ND + nidx];
                    y = Wb[(size_t)(k0 + 2 * w + 1) * ND + nidx];
                }
                rb[i] = make_float2(x, y);
            }
        } else {
#pragma unroll
            for (int i = 0; i < 4; i++) {
                int nidx = col0 + rr + i * 16;
                rb[i] = (kv && nidx < ND)
                    ? *(const float2*)&Wb[(size_t)nidx * KD + k0 + 2 * kw]
                    : make_float2(0.f, 0.f);
            }
        }
    };
    auto storeT = [&](int buf) {
#pragma unroll
        for (int i = 0; i < 4; i++) As2[buf][kw][rr + i * 16] = splitpack2(ra[i]);
        if (!TB) {
#pragma unroll
            for (int i = 0; i < 4; i++) Bs2[buf][kq + i * 4][nn] = splitpack2(rb[i]);
        } else {
#pragma unroll
            for (int i = 0; i < 4; i++) Bs2[buf][kw][rr + i * 16] = splitpack2(rb[i]);
        }
    };

    // 8 warps, warp tile 16(m) x 32(n)
    int wid = tid >> 5, lane = tid & 31;
    int m0w = (wid & 3) * 16;
    int n0w = (wid >> 2) * 32;
    int lr = lane >> 2, lc = lane & 3;

    float acc[4][4] = {};

    loadT(0);
    storeT(0);
    __syncthreads();

    for (int t = 0; t < NT; t++) {
        int cur = t & 1;
        if (t + 1 < NT) loadT(t + 1);
#pragma unroll
        for (int ks = 0; ks < 2; ks++) {   // two k16 steps per chunk
            int kb = ks * 8;
            uint2 wa0 = As2[cur][kb + lc][m0w + lr];
            uint2 wa1 = As2[cur][kb + lc][m0w + lr + 8];
            uint2 wa2 = As2[cur][kb + lc + 4][m0w + lr];
            uint2 wa3 = As2[cur][kb + lc + 4][m0w + lr + 8];
#pragma unroll
            for (int nt = 0; nt < 4; nt++) {
                uint2 wb0 = Bs2[cur][kb + lc][n0w + nt * 8 + lr];
                uint2 wb1 = Bs2[cur][kb + lc + 4][n0w + nt * 8 + lr];
                mma_bf16(acc[nt], wa0.x, wa1.x, wa2.x, wa3.x, wb0.x, wb1.x);
                mma_bf16(acc[nt], wa0.x, wa1.x, wa2.x, wa3.x, wb0.y, wb1.y);
                mma_bf16(acc[nt], wa0.y, wa1.y, wa2.y, wa3.y, wb0.x, wb1.x);
            }
        }
        if (t + 1 < NT) {
            storeT(cur ^ 1);
            __syncthreads();
        }
    }

    float epart = 0.f;
#pragma unroll
    for (int half = 0; half < 2; half++) {
        int rloc = m0w + lr + half * 8;
        int r = row0 + rloc;
        if (r >= count) continue;
        int atom = rows[rloc];
        size_t crow = (EPI == 0) ? (size_t)atom : ((size_t)m0 * MAXN + atom);
#pragma unroll
        for (int nt = 0; nt < 4; nt++) {
#pragma unroll
            for (int e = 0; e < 2; e++) {
                int n = col0 + n0w + nt * 8 + lc * 2 + e;
                if (n >= ND) continue;
                float v = acc[nt][half * 2 + e];
                if (EPI == 1) {
                    v = celu01(v + bias[(size_t)(m0 * NS + s) * ND + n]);
                    C[crow * ND + n] = v;
                } else if (EPI == 2) {
                    float h = H[crow * ND + n];
                    C[crow * ND + n] = v * dcelu_y(h);
                } else if (EPI == 3) {
                    // fused L3 + head: h3 kept in-register only
                    v = celu01(v + bias[(size_t)(m0 * NS + s) * ND + n]);
                    float w4 = W4e[(size_t)(m0 * NS + s) * ND + n];
                    C[crow * ND + n] = 0.125f * w4 * dcelu_y(v);   // g3 seed
                    epart += v * w4;                               // energy partial
                } else {
                    C[crow * ND + n] = v;
                }
            }
        }
    }
    if (EPI == 3) {
        ered[tid] = epart;
        __syncthreads();
#pragma unroll
        for (int o = 128; o > 0; o >>= 1) {
            if (tid < o) ered[tid] += ered[tid + o];
            __syncthreads();
        }
        if (tid == 0 && ered[0] != 0.f) atomicAdd(&g_energy, 0.125f * ered[0]);
        else if (tid == 0) atomicAdd(&g_energy, 0.125f * ered[0]);
    }
}

// ---------------- merged AEV backward (ghost-guarded) ----------------
__global__ void k_aev_bwd(const float* __restrict__ crd, const int* __restrict__ sp,
                          const int* __restrict__ sgp,
                          const int* __restrict__ idx, int P,
                          const int* __restrict__ tri, int T, int nbr) {
    if (blockIdx.x < nbr) {
        int p = blockIdx.x * 128 + threadIdx.x;
        if (p >= P) return;
        int i = idx[p], j = idx[P + p];
        bool vi = sgp[i] >= 0, vj = sgp[j] >= 0;
        if (!vi && !vj) return;
        float dx = crd[3 * j + 0] - crd[3 * i + 0];
        float dy = crd[3 * j + 1] - crd[3 * i + 1];
        float dz = crd[3 * j + 2] - crd[3 * i + 2];
        float dist = sqrtf(dx * dx + dy * dy + dz * dz);
        float fc = fcut(dist, 5.2f);
        float fcp = dfcut(dist, 5.2f);
        const float* gi = g_gaev + (size_t)i * AEVD + sp[j] * 16;
        const float* gj = g_gaev + (size_t)j * AEVD + sp[i] * 16;
        float dLdd = 0.f;
#pragma unroll
        for (int k = 0; k < 16; k++) {
            float mu = 0.8f + 0.275f * (float)k;
            float dm = dist - mu;
            float e = expf(-19.7f * dm * dm);
            float dr = 0.25f * e * (fmaf(-39.4f * dm, fc, fcp));
            float gsum = (vi ? gi[k] : 0.f) + (vj ? gj[k] : 0.f);
            dLdd += gsum * dr;
        }
        float cf = dLdd / dist;
        atomicAdd(&g_grad[3 * j + 0],  cf * dx);
        atomicAdd(&g_grad[3 * j + 1],  cf * dy);
        atomicAdd(&g_grad[3 * j + 2],  cf * dz);
        atomicAdd(&g_grad[3 * i + 0], -cf * dx);
        atomicAdd(&g_grad[3 * i + 1], -cf * dy);
        atomicAdd(&g_grad[3 * i + 2], -cf * dz);
    } else {
        int t = (blockIdx.x - nbr) * 128 + threadIdx.x;
        if (t >= T) return;
        int c = tri[t], a = tri[T + t], b = tri[2 * T + t];
        if (sgp[c] < 0) return;
        float v1x = crd[3 * a + 0] - crd[3 * c + 0];
        float v1y = crd[3 * a + 1] - crd[3 * c + 1];
        float v1z = crd[3 * a + 2] - crd[3 * c + 2];
        float v2x = crd[3 * b + 0] - crd[3 * c + 0];
        float v2y = crd[3 * b + 1] - crd[3 * c + 1];
        float v2z = crd[3 * b + 2] - crd[3 * c + 2];
        float d1 = sqrtf(v1x * v1x + v1y * v1y + v1z * v1z);
        float d2 = sqrtf(v2x * v2x + v2y * v2y + v2z * v2z);
        float id1 = 1.f / d1, id2 = 1.f / d2;
        float dot = v1x * v2x + v1y * v2y + v1z * v2z;
        float cosang = 0.95f * dot * id1 * id2;
        float ang = acosf(cosang);
        float fc1 = fcut(d1, 3.5f), fc2 = fcut(d2, 3.5f);
        float fc1p = dfcut(d1, 3.5f), fc2p = dfcut(d2, 3.5f);
        float fcj = fc1 * fc2;
        float u = 0.5f * (d1 + d2);

        float f1[4], df1[4];
#pragma unroll
        for (int z = 0; z < 4; z++) {
            float th = ang - ((float)z + 0.5f) * (PI_F / 4.f);
            float ct = cosf(th), st = sinf(th);
            float tt = 0.5f * (1.f + ct);
            float p13 = powf(tt, 13.1f);
            f1[z] = p13 * tt;
            df1[z] = 14.1f * p13 * (-0.5f * st);
        }
        float f2[8], df2[8];
#pragma unroll
        for (int s8 = 0; s8 < 8; s8++) {
            float dd = u - (0.8f + 0.3375f * (float)s8);
            f2[s8] = expf(-12.5f * dd * dd);
            df2[s8] = -25.f * dd * f2[s8];
        }
        int pidx = pair_index(sp[a], sp[b]);
        const float* g = g_gaev + (size_t)c * AEVD + 112 + pidx * 32;

        float Sg = 0.f, SdA = 0.f, Sdu = 0.f;
#pragma unroll
        for (int s8 = 0; s8 < 8; s8++) {
#pragma unroll
            for (int z = 0; z < 4; z++) {
                float gv = g[s8 * 4 + z];
                Sg  += gv * f2[s8] * f1[z];
                SdA += gv * f2[s8] * df1[z];
                Sdu += gv * df2[s8] * f1[z];
            }
        }
        float dLdA = 2.f * fcj * SdA;
        float dLdu = 2.f * fcj * Sdu;
        float dLdfc1 = 2.f * fc2 * Sg;
        float dLdfc2 = 2.f * fc1 * Sg;

        float dLdcos = dLdA * (-rsqrtf(fmaxf(1.f - cosang * cosang, 1e-12f)));
        float cA = 0.95f * id1 * id2;
        float cB1 = 0.95f * dot * id1 * id1 * id1 * id2;
        float cB2 = 0.95f * dot * id2 * id2 * id2 * id1;
        float r1 = (0.5f * dLdu + dLdfc1 * fc1p) * id1;
        float r2 = (0.5f * dLdu + dLdfc2 * fc2p) * id2;

        float g1x = dLdcos * (cA * v2x - cB1 * v1x) + r1 * v1x;
        float g1y = dLdcos * (cA * v2y - cB1 * v1y) + r1 * v1y;
        float g1z = dLdcos * (cA * v2z - cB1 * v1z) + r1 * v1z;
        float g2x = dLdcos * (cA * v1x - cB2 * v2x) + r2 * v2x;
        float g2y = dLdcos * (cA * v1y - cB2 * v2y) + r2 * v2y;
        float g2z = dLdcos * (cA * v1z - cB2 * v2z) + r2 * v2z;

        atomicAdd(&g_grad[3 * a + 0], g1x);
        atomicAdd(&g_grad[3 * a + 1], g1y);
        atomicAdd(&g_grad[3 * a + 2], g1z);
        atomicAdd(&g_grad[3 * b + 0], g2x);
        atomicAdd(&g_grad[3 * b + 1], g2y);
        atomicAdd(&g_grad[3 * b + 2], g2z);
        atomicAdd(&g_grad[3 * c + 0], -(g1x + g2x));
        atomicAdd(&g_grad[3 * c + 1], -(g1y + g2y));
        atomicAdd(&g_grad[3 * c + 2], -(g1z + g2z));
    }
}

// ---------------- finalize ----------------
__global__ void k_fin(float* __restrict__ out, int N, int out_size) {
    int i = blockIdx.x * blockDim.x + threadIdx.x;
    if (i >= out_size) return;
    if (i == 0) { out[0] = g_energy; return; }
    int k = i - 1;
    out[i] = (k < 3 * N) ? -g_grad[k] : 0.f;
}

// ---------------- host launcher ----------------
extern "C" void kernel_launch(void* const* d_in, const int* in_sizes, int n_in,
                              void* d_out, int out_size) {
    const int*   species = (const int*)d_in[0];
    const float* coords  = (const float*)d_in[1];
    const int*   idx12   = (const int*)d_in[2];
    const int*   tri     = (const int*)d_in[3];
    const int*   sgp     = (const int*)d_in[4];
    const float* W1 = (const float*)d_in[5];
    const float* b1 = (const float*)d_in[6];
    const float* W2 = (const float*)d_in[7];
    const float* b2 = (const float*)d_in[8];
    const float* W3 = (const float*)d_in[9];
    const float* b3 = (const float*)d_in[10];
    const float* W4 = (const float*)d_in[11];
    const float* b4 = (const float*)d_in[12];
    const float* sae = (const float*)d_in[13];
    int N = in_sizes[0];
    int P = in_sizes[2] / 2;
    int T = in_sizes[3] / 3;
    float* out = (float*)d_out;
    if (N > MAXN) return;

    float *p_aev, *p_gaev, *p_h1, *p_h2, *p_g1, *p_g2, *p_g3;
    cudaGetSymbolAddress((void**)&p_aev,  g_aev);
    cudaGetSymbolAddress((void**)&p_gaev, g_gaev);
    cudaGetSymbolAddress((void**)&p_h1,   g_h1);
    cudaGetSymbolAddress((void**)&p_h2,   g_h2);
    cudaGetSymbolAddress((void**)&p_g1,   g_g1);
    cudaGetSymbolAddress((void**)&p_g2,   g_g2);
    cudaGetSymbolAddress((void**)&p_g3,   g_g3);

    int nbr = (P + 127) / 128;
    int nba = (T + 127) / 128;

    k_zero<<<1024, 256>>>(N);
    k_build<<<(N + 255) / 256, 256>>>(sgp, sae, b4, N);
    k_scan<<<1, 32>>>();
    k_aev_fwd<<<nbr + nba, 128>>>(coords, species, idx12, P, tri, T, nbr);

    // forward MLP (L3 fused with head via EPI=3)
    k_gemm<1008, 256, 1, false, false, false><<<dim3(4, MAXTILES, 8), 256>>>(p_aev, W1, b1, nullptr, p_h1, nullptr);
    k_gemm<256,  192, 1, false, true,  false><<<dim3(3, MAXTILES, 8), 256>>>(p_h1,  W2, b2, nullptr, p_h2, nullptr);
    k_gemm<192,  160, 3, false, true,  false><<<dim3(3, MAXTILES, 8), 256>>>(p_h2,  W3, b3, nullptr, p_g3, W4);
    // backward MLP
    k_gemm<160,  192, 2, true,  true,  false><<<dim3(3, MAXTILES, 8), 256>>>(p_g3, W3, nullptr, p_h2, p_g2, nullptr);
    k_gemm<192,  256, 2, true,  true,  false><<<dim3(4, MAXTILES, 8), 256>>>(p_g2, W2, nullptr, p_h1, p_g1, nullptr);
    k_gemm<256, 1008, 0, true,  true,  true ><<<dim3(16, MAXTILES, 1), 256>>>(p_g1, W1, nullptr, nullptr, p_gaev, nullptr);
    // AEV backward -> forces
    k_aev_bwd<<<nbr + nba, 128>>>(coords, species, sgp, idx12, P, tri, T, nbr);

    k_fin<<<(out_size + 255) / 256, 256>>>(out, N, out_size);
}

// round 15
// speedup vs baseline: 1.0082x; 1.0082x over previous
#include <cuda_runtime.h>
#include <cuda_bf16.h>
#include <math.h>
#include <stdint.h>

#define MAXN 2744
#define AEVD 1008
#define NS 7
#define MAXTILES 56

// ---------------- scratch (static device globals) ----------------
__device__ float g_aev [(size_t)MAXN * AEVD];
__device__ float g_gaev[(size_t)MAXN * AEVD];
__device__ float g_h1[(size_t)8 * MAXN * 256];
__device__ float g_h2[(size_t)8 * MAXN * 192];
__device__ float g_g1[(size_t)8 * MAXN * 256];
__device__ float g_g2[(size_t)8 * MAXN * 192];
__device__ float g_g3[(size_t)8 * MAXN * 160];
__device__ float g_grad[MAXN * 3];
__device__ float g_energy;
__device__ int   g_cnt[NS];
__device__ int   g_list[NS * MAXN];
__device__ int   g_tilecnt;
__device__ int   g_tile_s[MAXTILES];
__device__ int   g_tile_r[MAXTILES];

#define PI_F 3.14159265358979323846f

__device__ __forceinline__ float celu01(float x) {
    return x > 0.f ? x : 0.1f * expm1f(10.f * x);
}
__device__ __forceinline__ float dcelu_y(float y) {
    return y > 0.f ? 1.f : fmaf(y, 10.f, 1.f);
}
__device__ __forceinline__ float fcut(float d, float rc) {
    return d < rc ? 0.5f * cosf(PI_F * d / rc) + 0.5f : 0.f;
}
__device__ __forceinline__ float dfcut(float d, float rc) {
    return d < rc ? -0.5f * (PI_F / rc) * sinf(PI_F * d / rc) : 0.f;
}
__device__ __forceinline__ int pair_index(int sa, int sb) {
    int lo = min(sa, sb), hi = max(sa, sb);
    return lo * NS - (lo * (lo - 1)) / 2 + (hi - lo);
}

// ---- bf16 split helpers ----
__device__ __forceinline__ uint2 splitpack2(float2 v) {
    __nv_bfloat162 h = __float22bfloat162_rn(v);
    float r0 = v.x - __low2float(h);
    float r1 = v.y - __high2float(h);
    __nv_bfloat162 l = __float22bfloat162_rn(make_float2(r0, r1));
    uint2 o;
    o.x = *reinterpret_cast<unsigned int*>(&h);
    o.y = *reinterpret_cast<unsigned int*>(&l);
    return o;
}
__device__ __forceinline__ void mma_bf16(float c[4], uint32_t a0, uint32_t a1,
                                         uint32_t a2, uint32_t a3,
                                         uint32_t b0, uint32_t b1) {
    asm("mma.sync.aligned.m16n8k16.row.col.f32.bf16.bf16.f32 "
        "{%0,%1,%2,%3}, {%4,%5,%6,%7}, {%8,%9}, {%0,%1,%2,%3};"
        : "+f"(c[0]), "+f"(c[1]), "+f"(c[2]), "+f"(c[3])
        : "r"(a0), "r"(a1), "r"(a2), "r"(a3), "r"(b0), "r"(b1));
}

// ---------------- init (g_gaev NOT zeroed; ghost rows guarded in bwd) ----------------
__global__ void k_zero(int N) {
    size_t na = (size_t)N * AEVD;
    size_t total = na + (size_t)3 * N;
    for (size_t i = (size_t)blockIdx.x * blockDim.x + threadIdx.x; i < total;
         i += (size_t)gridDim.x * blockDim.x) {
        if (i < na) g_aev[i] = 0.f;
        else        g_grad[i - na] = 0.f;
    }
    if (blockIdx.x == 0 && threadIdx.x < NS) g_cnt[threadIdx.x] = 0;
    if (blockIdx.x == 0 && threadIdx.x == 0) g_energy = 0.f;
}

// build species lists; fold SAE + ensemble-mean b4 into energy
__global__ void k_build(const int* __restrict__ sgp, const float* __restrict__ sae,
                        const float* __restrict__ b4, int N) {
    int i = blockIdx.x * blockDim.x + threadIdx.x;
    if (i >= N) return;
    int s = sgp[i];
    if (s >= 0) {
        int p = atomicAdd(&g_cnt[s], 1);
        g_list[s * MAXN + p] = i;
        float bsum = 0.f;
#pragma unroll
        for (int m = 0; m < 8; m++) bsum += b4[m * NS + s];
        atomicAdd(&g_energy, sae[s] + 0.125f * bsum);
    }
}

__global__ void k_scan() {
    if (threadIdx.x != 0) return;
    int t = 0;
    for (int s = 0; s < NS; s++) {
        int c = g_cnt[s];
        for (int r0 = 0; r0 < c && t < MAXTILES; r0 += 64) {
            g_tile_s[t] = s;
            g_tile_r[t] = r0;
            t++;
        }
    }
    g_tilecnt = t;
}

// ---------------- merged AEV forward ----------------
__global__ void k_aev_fwd(const float* __restrict__ crd, const int* __restrict__ sp,
                          const int* __restrict__ idx, int P,
                          const int* __restrict__ tri, int T, int nbr) {
    if (blockIdx.x < nbr) {
        int p = blockIdx.x * 128 + threadIdx.x;
        if (p >= P) return;
        int i = idx[p], j = idx[P + p];
        float dx = crd[3 * j + 0] - crd[3 * i + 0];
        float dy = crd[3 * j + 1] - crd[3 * i + 1];
        float dz = crd[3 * j + 2] - crd[3 * i + 2];
        float dist = sqrtf(dx * dx + dy * dy + dz * dz);
        float fc = fcut(dist, 5.2f);
        float* ai = g_aev + (size_t)i * AEVD + sp[j] * 16;
        float* aj = g_aev + (size_t)j * AEVD + sp[i] * 16;
#pragma unroll
        for (int k = 0; k < 16; k++) {
            float mu = 0.8f + 0.275f * (float)k;
            float dm = dist - mu;
            float r = 0.25f * expf(-19.7f * dm * dm) * fc;
            atomicAdd(ai + k, r);
            atomicAdd(aj + k, r);
        }
    } else {
        int t = (blockIdx.x - nbr) * 128 + threadIdx.x;
        if (t >= T) return;
        int c = tri[t], a = tri[T + t], b = tri[2 * T + t];
        float v1x = crd[3 * a + 0] - crd[3 * c + 0];
        float v1y = crd[3 * a + 1] - crd[3 * c + 1];
        float v1z = crd[3 * a + 2] - crd[3 * c + 2];
        float v2x = crd[3 * b + 0] - crd[3 * c + 0];
        float v2y = crd[3 * b + 1] - crd[3 * c + 1];
        float v2z = crd[3 * b + 2] - crd[3 * c + 2];
        float d1 = sqrtf(v1x * v1x + v1y * v1y + v1z * v1z);
        float d2 = sqrtf(v2x * v2x + v2y * v2y + v2z * v2z);
        float dot = v1x * v2x + v1y * v2y + v1z * v2z;
        float cosang = 0.95f * dot / (d1 * d2);
        float ang = acosf(cosang);
        float fcj = fcut(d1, 3.5f) * fcut(d2, 3.5f);
        float u = 0.5f * (d1 + d2);
        float f1[4];
#pragma unroll
        for (int z = 0; z < 4; z++) {
            float th = ang - ((float)z + 0.5f) * (PI_F / 4.f);
            float tt = 0.5f * (1.f + cosf(th));
            f1[z] = powf(tt, 14.1f);
        }
        float f2[8];
#pragma unroll
        for (int s8 = 0; s8 < 8; s8++) {
            float dd = u - (0.8f + 0.3375f * (float)s8);
            f2[s8] = expf(-12.5f * dd * dd);
        }
        int pidx = pair_index(sp[a], sp[b]);
        float* dst = g_aev + (size_t)c * AEVD + 112 + pidx * 32;
#pragma unroll
        for (int s8 = 0; s8 < 8; s8++)
#pragma unroll
            for (int z = 0; z < 4; z++)
                atomicAdd(dst + s8 * 4 + z, 2.f * f2[s8] * f1[z] * fcj);
    }
}

// ---------------- bf16-split (3-term) m16n8k16 GEMM, BK=16 (R13-proven loop) ----------------
// EPI: 1 = celu(x+bias) -> C ; 2 = x*dcelu(H) -> C ; 0 = plain SUMM ; 3 = fused L3+head
template <int KD, int ND, int EPI, bool TB, bool AENS, bool SUMM>
__global__ __launch_bounds__(256) void k_gemm(const float* __restrict__ A,
                                              const float* __restrict__ W,
                                              const float* __restrict__ bias,
                                              const float* __restrict__ H,
                                              float* __restrict__ C,
                                              const float* __restrict__ W4e) {
    const int BM = 64, BN = 64, BK = 16;
    const int KT = KD / BK;
    const int NT = (SUMM ? 8 : 1) * KT;
    int ti = blockIdx.y;
    if (ti >= g_tilecnt) return;
    int s = g_tile_s[ti];
    int row0 = g_tile_r[ti];
    int m0 = SUMM ? 0 : blockIdx.z;
    int count = g_cnt[s];
    int col0 = blockIdx.x * BN;

    __shared__ uint2 As2[2][8][BM + 4];
    __shared__ uint2 Bs2[2][8][BN + 4];
    __shared__ int rows[BM];
    __shared__ float ered[256];

    int tid = threadIdx.x;
    if (tid < BM) {
        int r = row0 + tid;
        rows[tid] = (r < count) ? g_list[s * MAXN + r] : -1;
    }
    __syncthreads();

    int kw = tid & 7,  rr = tid >> 3;
    int nn = tid & 63, kq = tid >> 6;

    int arow[2];
    arow[0] = rows[rr];
    arow[1] = rows[rr + 32];

    float2 ra[2], rb[2];

    auto loadT = [&](int t) {
        int m  = SUMM ? (t / KT) : m0;
        int k0 = (SUMM ? (t % KT) : t) * BK;
        const float* Wb = W + (size_t)(m * NS + s) * KD * ND;
        const float* Ab = A + (AENS ? (size_t)m * MAXN * KD : (size_t)0);
#pragma unroll
        for (int i = 0; i < 2; i++)
            ra[i] = (arow[i] >= 0)
                ? *(const float2*)&Ab[(size_t)arow[i] * KD + k0 + 2 * kw]
                : make_float2(0.f, 0.f);
        if (!TB) {
#pragma unroll
            for (int i = 0; i < 2; i++) {
                int w = kq + i * 4;
                int nidx = col0 + nn;
                float x = 0.f, y = 0.f;
                if (nidx < ND) {
                    x = Wb[(size_t)(k0 + 2 * w) * ND + nidx];
                    y = Wb[(size_t)(k0 + 2 * w + 1) * ND + nidx];
                }
                rb[i] = make_float2(x, y);
            }
        } else {
#pragma unroll
            for (int i = 0; i < 2; i++) {
                int nidx = col0 + rr + i * 32;
                rb[i] = (nidx < ND)
                    ? *(const float2*)&Wb[(size_t)nidx * KD + k0 + 2 * kw]
                    : make_float2(0.f, 0.f);
            }
        }
    };
    auto storeT = [&](int buf) {
#pragma unroll
        for (int i = 0; i < 2; i++) As2[buf][kw][rr + i * 32] = splitpack2(ra[i]);
        if (!TB) {
#pragma unroll
            for (int i = 0; i < 2; i++) Bs2[buf][kq + i * 4][nn] = splitpack2(rb[i]);
        } else {
#pragma unroll
            for (int i = 0; i < 2; i++) Bs2[buf][kw][rr + i * 32] = splitpack2(rb[i]);
        }
    };

    int wid = tid >> 5, lane = tid & 31;
    int m0w = (wid & 3) * 16;
    int n0w = (wid >> 2) * 32;
    int lr = lane >> 2, lc = lane & 3;

    float acc[4][4] = {};

    loadT(0);
    storeT(0);
    __syncthreads();

    for (int t = 0; t < NT; t++) {
        int cur = t & 1;
        if (t + 1 < NT) loadT(t + 1);
        uint2 wa0 = As2[cur][lc][m0w + lr];
        uint2 wa1 = As2[cur][lc][m0w + lr + 8];
        uint2 wa2 = As2[cur][lc + 4][m0w + lr];
        uint2 wa3 = As2[cur][lc + 4][m0w + lr + 8];
#pragma unroll
        for (int nt = 0; nt < 4; nt++) {
            uint2 wb0 = Bs2[cur][lc][n0w + nt * 8 + lr];
            uint2 wb1 = Bs2[cur][lc + 4][n0w + nt * 8 + lr];
            mma_bf16(acc[nt], wa0.x, wa1.x, wa2.x, wa3.x, wb0.x, wb1.x);
            mma_bf16(acc[nt], wa0.x, wa1.x, wa2.x, wa3.x, wb0.y, wb1.y);
            mma_bf16(acc[nt], wa0.y, wa1.y, wa2.y, wa3.y, wb0.x, wb1.x);
        }
        if (t + 1 < NT) {
            storeT(cur ^ 1);
            __syncthreads();
        }
    }

    float epart = 0.f;
#pragma unroll
    for (int half = 0; half < 2; half++) {
        int rloc = m0w + lr + half * 8;
        int r = row0 + rloc;
        if (r >= count) continue;
        int atom = rows[rloc];
        size_t crow = (EPI == 0) ? (size_t)atom : ((size_t)m0 * MAXN + atom);
#pragma unroll
        for (int nt = 0; nt < 4; nt++) {
#pragma unroll
            for (int e = 0; e < 2; e++) {
                int n = col0 + n0w + nt * 8 + lc * 2 + e;
                if (n >= ND) continue;
                float v = acc[nt][half * 2 + e];
                if (EPI == 1) {
                    v = celu01(v + bias[(size_t)(m0 * NS + s) * ND + n]);
                    C[crow * ND + n] = v;
                } else if (EPI == 2) {
                    float h = H[crow * ND + n];
                    C[crow * ND + n] = v * dcelu_y(h);
                } else if (EPI == 3) {
                    // fused L3 + head: h3 kept in-register only
                    v = celu01(v + bias[(size_t)(m0 * NS + s) * ND + n]);
                    float w4 = W4e[(size_t)(m0 * NS + s) * ND + n];
                    C[crow * ND + n] = 0.125f * w4 * dcelu_y(v);   // g3 seed
                    epart += v * w4;                               // energy partial
                } else {
                    C[crow * ND + n] = v;
                }
            }
        }
    }
    if (EPI == 3) {
        ered[tid] = epart;
        __syncthreads();
#pragma unroll
        for (int o = 128; o > 0; o >>= 1) {
            if (tid < o) ered[tid] += ered[tid + o];
            __syncthreads();
        }
        if (tid == 0) atomicAdd(&g_energy, 0.125f * ered[0]);
    }
}

// ---------------- merged AEV backward (ghost-guarded) ----------------
__global__ void k_aev_bwd(const float* __restrict__ crd, const int* __restrict__ sp,
                          const int* __restrict__ sgp,
                          const int* __restrict__ idx, int P,
                          const int* __restrict__ tri, int T, int nbr) {
    if (blockIdx.x < nbr) {
        int p = blockIdx.x * 128 + threadIdx.x;
        if (p >= P) return;
        int i = idx[p], j = idx[P + p];
        bool vi = sgp[i] >= 0, vj = sgp[j] >= 0;
        if (!vi && !vj) return;
        float dx = crd[3 * j + 0] - crd[3 * i + 0];
        float dy = crd[3 * j + 1] - crd[3 * i + 1];
        float dz = crd[3 * j + 2] - crd[3 * i + 2];
        float dist = sqrtf(dx * dx + dy * dy + dz * dz);
        float fc = fcut(dist, 5.2f);
        float fcp = dfcut(dist, 5.2f);
        const float* gi = g_gaev + (size_t)i * AEVD + sp[j] * 16;
        const float* gj = g_gaev + (size_t)j * AEVD + sp[i] * 16;
        float dLdd = 0.f;
#pragma unroll
        for (int k = 0; k < 16; k++) {
            float mu = 0.8f + 0.275f * (float)k;
            float dm = dist - mu;
            float e = expf(-19.7f * dm * dm);
            float dr = 0.25f * e * (fmaf(-39.4f * dm, fc, fcp));
            float gsum = (vi ? gi[k] : 0.f) + (vj ? gj[k] : 0.f);
            dLdd += gsum * dr;
        }
        float cf = dLdd / dist;
        atomicAdd(&g_grad[3 * j + 0],  cf * dx);
        atomicAdd(&g_grad[3 * j + 1],  cf * dy);
        atomicAdd(&g_grad[3 * j + 2],  cf * dz);
        atomicAdd(&g_grad[3 * i + 0], -cf * dx);
        atomicAdd(&g_grad[3 * i + 1], -cf * dy);
        atomicAdd(&g_grad[3 * i + 2], -cf * dz);
    } else {
        int t = (blockIdx.x - nbr) * 128 + threadIdx.x;
        if (t >= T) return;
        int c = tri[t], a = tri[T + t], b = tri[2 * T + t];
        if (sgp[c] < 0) return;
        float v1x = crd[3 * a + 0] - crd[3 * c + 0];
        float v1y = crd[3 * a + 1] - crd[3 * c + 1];
        float v1z = crd[3 * a + 2] - crd[3 * c + 2];
        float v2x = crd[3 * b + 0] - crd[3 * c + 0];
        float v2y = crd[3 * b + 1] - crd[3 * c + 1];
        float v2z = crd[3 * b + 2] - crd[3 * c + 2];
        float d1 = sqrtf(v1x * v1x + v1y * v1y + v1z * v1z);
        float d2 = sqrtf(v2x * v2x + v2y * v2y + v2z * v2z);
        float id1 = 1.f / d1, id2 = 1.f / d2;
        float dot = v1x * v2x + v1y * v2y + v1z * v2z;
        float cosang = 0.95f * dot * id1 * id2;
        float ang = acosf(cosang);
        float fc1 = fcut(d1, 3.5f), fc2 = fcut(d2, 3.5f);
        float fc1p = dfcut(d1, 3.5f), fc2p = dfcut(d2, 3.5f);
        float fcj = fc1 * fc2;
        float u = 0.5f * (d1 + d2);

        float f1[4], df1[4];
#pragma unroll
        for (int z = 0; z < 4; z++) {
            float th = ang - ((float)z + 0.5f) * (PI_F / 4.f);
            float ct = cosf(th), st = sinf(th);
            float tt = 0.5f * (1.f + ct);
            float p13 = powf(tt, 13.1f);
            f1[z] = p13 * tt;
            df1[z] = 14.1f * p13 * (-0.5f * st);
        }
        float f2[8], df2[8];
#pragma unroll
        for (int s8 = 0; s8 < 8; s8++) {
            float dd = u - (0.8f + 0.3375f * (float)s8);
            f2[s8] = expf(-12.5f * dd * dd);
            df2[s8] = -25.f * dd * f2[s8];
        }
        int pidx = pair_index(sp[a], sp[b]);
        const float* g = g_gaev + (size_t)c * AEVD + 112 + pidx * 32;

        float Sg = 0.f, SdA = 0.f, Sdu = 0.f;
#pragma unroll
        for (int s8 = 0; s8 < 8; s8++) {
#pragma unroll
            for (int z = 0; z < 4; z++) {
                float gv = g[s8 * 4 + z];
                Sg  += gv * f2[s8] * f1[z];
                SdA += gv * f2[s8] * df1[z];
                Sdu += gv * df2[s8] * f1[z];
            }
        }
        float dLdA = 2.f * fcj * SdA;
        float dLdu = 2.f * fcj * Sdu;
        float dLdfc1 = 2.f * fc2 * Sg;
        float dLdfc2 = 2.f * fc1 * Sg;

        float dLdcos = dLdA * (-rsqrtf(fmaxf(1.f - cosang * cosang, 1e-12f)));
        float cA = 0.95f * id1 * id2;
        float cB1 = 0.95f * dot * id1 * id1 * id1 * id2;
        float cB2 = 0.95f * dot * id2 * id2 * id2 * id1;
        float r1 = (0.5f * dLdu + dLdfc1 * fc1p) * id1;
        float r2 = (0.5f * dLdu + dLdfc2 * fc2p) * id2;

        float g1x = dLdcos * (cA * v2x - cB1 * v1x) + r1 * v1x;
        float g1y = dLdcos * (cA * v2y - cB1 * v1y) + r1 * v1y;
        float g1z = dLdcos * (cA * v2z - cB1 * v1z) + r1 * v1z;
        float g2x = dLdcos * (cA * v1x - cB2 * v2x) + r2 * v2x;
        float g2y = dLdcos * (cA * v1y - cB2 * v2y) + r2 * v2y;
        float g2z = dLdcos * (cA * v1z - cB2 * v2z) + r2 * v2z;

        atomicAdd(&g_grad[3 * a + 0], g1x);
        atomicAdd(&g_grad[3 * a + 1], g1y);
        atomicAdd(&g_grad[3 * a + 2], g1z);
        atomicAdd(&g_grad[3 * b + 0], g2x);
        atomicAdd(&g_grad[3 * b + 1], g2y);
        atomicAdd(&g_grad[3 * b + 2], g2z);
        atomicAdd(&g_grad[3 * c + 0], -(g1x + g2x));
        atomicAdd(&g_grad[3 * c + 1], -(g1y + g2y));
        atomicAdd(&g_grad[3 * c + 2], -(g1z + g2z));
    }
}

// ---------------- finalize ----------------
__global__ void k_fin(float* __restrict__ out, int N, int out_size) {
    int i = blockIdx.x * blockDim.x + threadIdx.x;
    if (i >= out_size) return;
    if (i == 0) { out[0] = g_energy; return; }
    int k = i - 1;
    out[i] = (k < 3 * N) ? -g_grad[k] : 0.f;
}

// ---------------- host launcher ----------------
extern "C" void kernel_launch(void* const* d_in, const int* in_sizes, int n_in,
                              void* d_out, int out_size) {
    const int*   species = (const int*)d_in[0];
    const float* coords  = (const float*)d_in[1];
    const int*   idx12   = (const int*)d_in[2];
    const int*   tri     = (const int*)d_in[3];
    const int*   sgp     = (const int*)d_in[4];
    const float* W1 = (const float*)d_in[5];
    const float* b1 = (const float*)d_in[6];
    const float* W2 = (const float*)d_in[7];
    const float* b2 = (const float*)d_in[8];
    const float* W3 = (const float*)d_in[9];
    const float* b3 = (const float*)d_in[10];
    const float* W4 = (const float*)d_in[11];
    const float* b4 = (const float*)d_in[12];
    const float* sae = (const float*)d_in[13];
    int N = in_sizes[0];
    int P = in_sizes[2] / 2;
    int T = in_sizes[3] / 3;
    float* out = (float*)d_out;
    if (N > MAXN) return;

    float *p_aev, *p_gaev, *p_h1, *p_h2, *p_g1, *p_g2, *p_g3;
    cudaGetSymbolAddress((void**)&p_aev,  g_aev);
    cudaGetSymbolAddress((void**)&p_gaev, g_gaev);
    cudaGetSymbolAddress((void**)&p_h1,   g_h1);
    cudaGetSymbolAddress((void**)&p_h2,   g_h2);
    cudaGetSymbolAddress((void**)&p_g1,   g_g1);
    cudaGetSymbolAddress((void**)&p_g2,   g_g2);
    cudaGetSymbolAddress((void**)&p_g3,   g_g3);

    int nbr = (P + 127) / 128;
    int nba = (T + 127) / 128;

    k_zero<<<1024, 256>>>(N);
    k_build<<<(N + 255) / 256, 256>>>(sgp, sae, b4, N);
    k_scan<<<1, 32>>>();
    k_aev_fwd<<<nbr + nba, 128>>>(coords, species, idx12, P, tri, T, nbr);

    // forward MLP (L3 fused with head via EPI=3)
    k_gemm<1008, 256, 1, false, false, false><<<dim3(4, MAXTILES, 8), 256>>>(p_aev, W1, b1, nullptr, p_h1, nullptr);
    k_gemm<256,  192, 1, false, true,  false><<<dim3(3, MAXTILES, 8), 256>>>(p_h1,  W2, b2, nullptr, p_h2, nullptr);
    k_gemm<192,  160, 3, false, true,  false><<<dim3(3, MAXTILES, 8), 256>>>(p_h2,  W3, b3, nullptr, p_g3, W4);
    // backward MLP
    k_gemm<160,  192, 2, true,  true,  false><<<dim3(3, MAXTILES, 8), 256>>>(p_g3, W3, nullptr, p_h2, p_g2, nullptr);
    k_gemm<192,  256, 2, true,  true,  false><<<dim3(4, MAXTILES, 8), 256>>>(p_g2, W2, nullptr, p_h1, p_g1, nullptr);
    k_gemm<256, 1008, 0, true,  true,  true ><<<dim3(16, MAXTILES, 1), 256>>>(p_g1, W1, nullptr, nullptr, p_gaev, nullptr);
    // AEV backward -> forces
    k_aev_bwd<<<nbr + nba, 128>>>(coords, species, sgp, idx12, P, tri, T, nbr);

    k_fin<<<(out_size + 255) / 256, 256>>>(out, N, out_size);
}

// round 16
// speedup vs baseline: 1.0416x; 1.0331x over previous
#include <cuda_runtime.h>
#include <cuda_bf16.h>
#include <math.h>
#include <stdint.h>

#define MAXN 2744
#define AEVD 1008
#define NS 7
#define MAXTILES 56

// ---------------- scratch (static device globals) ----------------
__device__ float g_aev [(size_t)MAXN * AEVD];
__device__ float g_gaev[(size_t)MAXN * AEVD];
__device__ float g_h1[(size_t)8 * MAXN * 256];
__device__ float g_h2[(size_t)8 * MAXN * 192];
__device__ float g_g1[(size_t)8 * MAXN * 256];
__device__ float g_g2[(size_t)8 * MAXN * 192];
__device__ float g_g3[(size_t)8 * MAXN * 160];
__device__ float g_grad[MAXN * 3];
__device__ float g_energy;
__device__ int   g_cnt[NS];
__device__ int   g_list[NS * MAXN];
__device__ int   g_tilecnt;
__device__ int   g_tile_s[MAXTILES];
__device__ int   g_tile_r[MAXTILES];

#define PI_F 3.14159265358979323846f

__device__ __forceinline__ float celu01(float x) {
    return x > 0.f ? x : 0.1f * expm1f(10.f * x);
}
__device__ __forceinline__ float dcelu_y(float y) {
    return y > 0.f ? 1.f : fmaf(y, 10.f, 1.f);
}
__device__ __forceinline__ float fcut(float d, float rc) {
    return d < rc ? 0.5f * cosf(PI_F * d / rc) + 0.5f : 0.f;
}
__device__ __forceinline__ float dfcut(float d, float rc) {
    return d < rc ? -0.5f * (PI_F / rc) * sinf(PI_F * d / rc) : 0.f;
}
__device__ __forceinline__ int pair_index(int sa, int sb) {
    int lo = min(sa, sb), hi = max(sa, sb);
    return lo * NS - (lo * (lo - 1)) / 2 + (hi - lo);
}

// ---- bf16 split helpers ----
__device__ __forceinline__ uint2 splitpack2(float2 v) {
    __nv_bfloat162 h = __float22bfloat162_rn(v);
    float r0 = v.x - __low2float(h);
    float r1 = v.y - __high2float(h);
    __nv_bfloat162 l = __float22bfloat162_rn(make_float2(r0, r1));
    uint2 o;
    o.x = *reinterpret_cast<unsigned int*>(&h);
    o.y = *reinterpret_cast<unsigned int*>(&l);
    return o;
}
__device__ __forceinline__ void mma_bf16(float c[4], uint32_t a0, uint32_t a1,
                                         uint32_t a2, uint32_t a3,
                                         uint32_t b0, uint32_t b1) {
    asm("mma.sync.aligned.m16n8k16.row.col.f32.bf16.bf16.f32 "
        "{%0,%1,%2,%3}, {%4,%5,%6,%7}, {%8,%9}, {%0,%1,%2,%3};"
        : "+f"(c[0]), "+f"(c[1]), "+f"(c[2]), "+f"(c[3])
        : "r"(a0), "r"(a1), "r"(a2), "r"(a3), "r"(b0), "r"(b1));
}

// ---------------- init (g_gaev NOT zeroed; ghost rows guarded in bwd) ----------------
__global__ void k_zero(int N) {
    size_t na = (size_t)N * AEVD;
    size_t total = na + (size_t)3 * N;
    for (size_t i = (size_t)blockIdx.x * blockDim.x + threadIdx.x; i < total;
         i += (size_t)gridDim.x * blockDim.x) {
        if (i < na) g_aev[i] = 0.f;
        else        g_grad[i - na] = 0.f;
    }
    if (blockIdx.x == 0 && threadIdx.x == 0) g_energy = 0.f;
}

// single-block prep: count -> scan+tile table -> fill lists -> energy constant
__global__ void k_prep(const int* __restrict__ sgp, const float* __restrict__ sae,
                       const float* __restrict__ b4, int N) {
    __shared__ int scnt[NS], scur[NS];
    __shared__ float sb4[NS];
    __shared__ float ered[1024];
    int t = threadIdx.x;
    if (t < NS) {
        scnt[t] = 0; scur[t] = 0;
        float bs = 0.f;
#pragma unroll
        for (int m = 0; m < 8; m++) bs += b4[m * NS + t];
        sb4[t] = sae[t] + 0.125f * bs;
    }
    __syncthreads();
    float ep = 0.f;
    for (int i = t; i < N; i += 1024) {
        int s = sgp[i];
        if (s >= 0) { atomicAdd(&scnt[s], 1); ep += sb4[s]; }
    }
    __syncthreads();
    if (t == 0) {
        int tt = 0;
        for (int s = 0; s < NS; s++) {
            g_cnt[s] = scnt[s];
            for (int r0 = 0; r0 < scnt[s] && tt < MAXTILES; r0 += 64) {
                g_tile_s[tt] = s;
                g_tile_r[tt] = r0;
                tt++;
            }
        }
        g_tilecnt = tt;
    }
    __syncthreads();
    for (int i = t; i < N; i += 1024) {
        int s = sgp[i];
        if (s >= 0) {
            int p = atomicAdd(&scur[s], 1);
            g_list[s * MAXN + p] = i;
        }
    }
    ered[t] = ep;
    __syncthreads();
#pragma unroll
    for (int o = 512; o > 0; o >>= 1) {
        if (t < o) ered[t] += ered[t + o];
        __syncthreads();
    }
    if (t == 0) atomicAdd(&g_energy, ered[0]);
}

// ---------------- merged AEV forward ----------------
__global__ void k_aev_fwd(const float* __restrict__ crd, const int* __restrict__ sp,
                          const int* __restrict__ idx, int P,
                          const int* __restrict__ tri, int T, int nbr) {
    if (blockIdx.x < nbr) {
        int p = blockIdx.x * 128 + threadIdx.x;
        if (p >= P) return;
        int i = idx[p], j = idx[P + p];
        float dx = crd[3 * j + 0] - crd[3 * i + 0];
        float dy = crd[3 * j + 1] - crd[3 * i + 1];
        float dz = crd[3 * j + 2] - crd[3 * i + 2];
        float dist = sqrtf(dx * dx + dy * dy + dz * dz);
        float fc = fcut(dist, 5.2f);
        float* ai = g_aev + (size_t)i * AEVD + sp[j] * 16;
        float* aj = g_aev + (size_t)j * AEVD + sp[i] * 16;
#pragma unroll
        for (int k = 0; k < 16; k++) {
            float mu = 0.8f + 0.275f * (float)k;
            float dm = dist - mu;
            float r = 0.25f * expf(-19.7f * dm * dm) * fc;
            atomicAdd(ai + k, r);
            atomicAdd(aj + k, r);
        }
    } else {
        int t = (blockIdx.x - nbr) * 128 + threadIdx.x;
        if (t >= T) return;
        int c = tri[t], a = tri[T + t], b = tri[2 * T + t];
        float v1x = crd[3 * a + 0] - crd[3 * c + 0];
        float v1y = crd[3 * a + 1] - crd[3 * c + 1];
        float v1z = crd[3 * a + 2] - crd[3 * c + 2];
        float v2x = crd[3 * b + 0] - crd[3 * c + 0];
        float v2y = crd[3 * b + 1] - crd[3 * c + 1];
        float v2z = crd[3 * b + 2] - crd[3 * c + 2];
        float d1 = sqrtf(v1x * v1x + v1y * v1y + v1z * v1z);
        float d2 = sqrtf(v2x * v2x + v2y * v2y + v2z * v2z);
        float dot = v1x * v2x + v1y * v2y + v1z * v2z;
        float cosang = 0.95f * dot / (d1 * d2);
        float ang = acosf(cosang);
        float fcj = fcut(d1, 3.5f) * fcut(d2, 3.5f);
        float u = 0.5f * (d1 + d2);
        float f1[4];
#pragma unroll
        for (int z = 0; z < 4; z++) {
            float th = ang - ((float)z + 0.5f) * (PI_F / 4.f);
            float tt = 0.5f * (1.f + cosf(th));
            f1[z] = powf(tt, 14.1f);
        }
        float f2[8];
#pragma unroll
        for (int s8 = 0; s8 < 8; s8++) {
            float dd = u - (0.8f + 0.3375f * (float)s8);
            f2[s8] = expf(-12.5f * dd * dd);
        }
        int pidx = pair_index(sp[a], sp[b]);
        float* dst = g_aev + (size_t)c * AEVD + 112 + pidx * 32;
#pragma unroll
        for (int s8 = 0; s8 < 8; s8++)
#pragma unroll
            for (int z = 0; z < 4; z++)
                atomicAdd(dst + s8 * 4 + z, 2.f * f2[s8] * f1[z] * fcj);
    }
}

// ---------------- bf16-split (3-term) m16n8k16 GEMM, BK=16, 3 CTAs/SM ----------------
// EPI: 1 = celu(x+bias) -> C ; 2 = x*dcelu(H) -> C ; 0 = plain SUMM ; 3 = fused L3+head
template <int KD, int ND, int EPI, bool TB, bool AENS, bool SUMM>
__global__ __launch_bounds__(256, 3) void k_gemm(const float* __restrict__ A,
                                                 const float* __restrict__ W,
                                                 const float* __restrict__ bias,
                                                 const float* __restrict__ H,
                                                 float* __restrict__ C,
                                                 const float* __restrict__ W4e) {
    const int BM = 64, BN = 64, BK = 16;
    const int KT = KD / BK;
    const int NT = (SUMM ? 8 : 1) * KT;
    int ti = blockIdx.y;
    if (ti >= g_tilecnt) return;
    int s = g_tile_s[ti];
    int row0 = g_tile_r[ti];
    int m0 = SUMM ? 0 : blockIdx.z;
    int count = g_cnt[s];
    int col0 = blockIdx.x * BN;

    __shared__ uint2 As2[2][8][BM + 4];
    __shared__ uint2 Bs2[2][8][BN + 4];
    __shared__ int rows[BM];
    __shared__ float ered[256];

    int tid = threadIdx.x;
    if (tid < BM) {
        int r = row0 + tid;
        rows[tid] = (r < count) ? g_list[s * MAXN + r] : -1;
    }
    __syncthreads();

    int kw = tid & 7,  rr = tid >> 3;
    int nn = tid & 63, kq = tid >> 6;

    int arow[2];
    arow[0] = rows[rr];
    arow[1] = rows[rr + 32];

    float2 ra[2], rb[2];

    auto loadT = [&](int t) {
        int m  = SUMM ? (t / KT) : m0;
        int k0 = (SUMM ? (t % KT) : t) * BK;
        const float* Wb = W + (size_t)(m * NS + s) * KD * ND;
        const float* Ab = A + (AENS ? (size_t)m * MAXN * KD : (size_t)0);
#pragma unroll
        for (int i = 0; i < 2; i++)
            ra[i] = (arow[i] >= 0)
                ? *(const float2*)&Ab[(size_t)arow[i] * KD + k0 + 2 * kw]
                : make_float2(0.f, 0.f);
        if (!TB) {
#pragma unroll
            for (int i = 0; i < 2; i++) {
                int w = kq + i * 4;
                int nidx = col0 + nn;
                float x = 0.f, y = 0.f;
                if (nidx < ND) {
                    x = Wb[(size_t)(k0 + 2 * w) * ND + nidx];
                    y = Wb[(size_t)(k0 + 2 * w + 1) * ND + nidx];
                }
                rb[i] = make_float2(x, y);
            }
        } else {
#pragma unroll
            for (int i = 0; i < 2; i++) {
                int nidx = col0 + rr + i * 32;
                rb[i] = (nidx < ND)
                    ? *(const float2*)&Wb[(size_t)nidx * KD + k0 + 2 * kw]
                    : make_float2(0.f, 0.f);
            }
        }
    };
    auto storeT = [&](int buf) {
#pragma unroll
        for (int i = 0; i < 2; i++) As2[buf][kw][rr + i * 32] = splitpack2(ra[i]);
        if (!TB) {
#pragma unroll
            for (int i = 0; i < 2; i++) Bs2[buf][kq + i * 4][nn] = splitpack2(rb[i]);
        } else {
#pragma unroll
            for (int i = 0; i < 2; i++) Bs2[buf][kw][rr + i * 32] = splitpack2(rb[i]);
        }
    };

    int wid = tid >> 5, lane = tid & 31;
    int m0w = (wid & 3) * 16;
    int n0w = (wid >> 2) * 32;
    int lr = lane >> 2, lc = lane & 3;

    float acc[4][4] = {};

    loadT(0);
    storeT(0);
    __syncthreads();

    for (int t = 0; t < NT; t++) {
        int cur = t & 1;
        if (t + 1 < NT) loadT(t + 1);
        uint2 wa0 = As2[cur][lc][m0w + lr];
        uint2 wa1 = As2[cur][lc][m0w + lr + 8];
        uint2 wa2 = As2[cur][lc + 4][m0w + lr];
        uint2 wa3 = As2[cur][lc + 4][m0w + lr + 8];
#pragma unroll
        for (int nt = 0; nt < 4; nt++) {
            uint2 wb0 = Bs2[cur][lc][n0w + nt * 8 + lr];
            uint2 wb1 = Bs2[cur][lc + 4][n0w + nt * 8 + lr];
            mma_bf16(acc[nt], wa0.x, wa1.x, wa2.x, wa3.x, wb0.x, wb1.x);
            mma_bf16(acc[nt], wa0.x, wa1.x, wa2.x, wa3.x, wb0.y, wb1.y);
            mma_bf16(acc[nt], wa0.y, wa1.y, wa2.y, wa3.y, wb0.x, wb1.x);
        }
        if (t + 1 < NT) {
            storeT(cur ^ 1);
            __syncthreads();
        }
    }

    float epart = 0.f;
#pragma unroll
    for (int half = 0; half < 2; half++) {
        int rloc = m0w + lr + half * 8;
        int r = row0 + rloc;
        if (r >= count) continue;
        int atom = rows[rloc];
        size_t crow = (EPI == 0) ? (size_t)atom : ((size_t)m0 * MAXN + atom);
#pragma unroll
        for (int nt = 0; nt < 4; nt++) {
#pragma unroll
            for (int e = 0; e < 2; e++) {
                int n = col0 + n0w + nt * 8 + lc * 2 + e;
                if (n >= ND) continue;
                float v = acc[nt][half * 2 + e];
                if (EPI == 1) {
                    v = celu01(v + bias[(size_t)(m0 * NS + s) * ND + n]);
                    C[crow * ND + n] = v;
                } else if (EPI == 2) {
                    float h = H[crow * ND + n];
                    C[crow * ND + n] = v * dcelu_y(h);
                } else if (EPI == 3) {
                    v = celu01(v + bias[(size_t)(m0 * NS + s) * ND + n]);
                    float w4 = W4e[(size_t)(m0 * NS + s) * ND + n];
                    C[crow * ND + n] = 0.125f * w4 * dcelu_y(v);
                    epart += v * w4;
                } else {
                    C[crow * ND + n] = v;
                }
            }
        }
    }
    if (EPI == 3) {
        ered[tid] = epart;
        __syncthreads();
#pragma unroll
        for (int o = 128; o > 0; o >>= 1) {
            if (tid < o) ered[tid] += ered[tid + o];
            __syncthreads();
        }
        if (tid == 0) atomicAdd(&g_energy, 0.125f * ered[0]);
    }
}

// ---------------- merged AEV backward (ghost-guarded) ----------------
__global__ void k_aev_bwd(const float* __restrict__ crd, const int* __restrict__ sp,
                          const int* __restrict__ sgp,
                          const int* __restrict__ idx, int P,
                          const int* __restrict__ tri, int T, int nbr) {
    if (blockIdx.x < nbr) {
        int p = blockIdx.x * 128 + threadIdx.x;
        if (p >= P) return;
        int i = idx[p], j = idx[P + p];
        bool vi = sgp[i] >= 0, vj = sgp[j] >= 0;
        if (!vi && !vj) return;
        float dx = crd[3 * j + 0] - crd[3 * i + 0];
        float dy = crd[3 * j + 1] - crd[3 * i + 1];
        float dz = crd[3 * j + 2] - crd[3 * i + 2];
        float dist = sqrtf(dx * dx + dy * dy + dz * dz);
        float fc = fcut(dist, 5.2f);
        float fcp = dfcut(dist, 5.2f);
        const float* gi = g_gaev + (size_t)i * AEVD + sp[j] * 16;
        const float* gj = g_gaev + (size_t)j * AEVD + sp[i] * 16;
        float dLdd = 0.f;
#pragma unroll
        for (int k = 0; k < 16; k++) {
            float mu = 0.8f + 0.275f * (float)k;
            float dm = dist - mu;
            float e = expf(-19.7f * dm * dm);
            float dr = 0.25f * e * (fmaf(-39.4f * dm, fc, fcp));
            float gsum = (vi ? gi[k] : 0.f) + (vj ? gj[k] : 0.f);
            dLdd += gsum * dr;
        }
        float cf = dLdd / dist;
        atomicAdd(&g_grad[3 * j + 0],  cf * dx);
        atomicAdd(&g_grad[3 * j + 1],  cf * dy);
        atomicAdd(&g_grad[3 * j + 2],  cf * dz);
        atomicAdd(&g_grad[3 * i + 0], -cf * dx);
        atomicAdd(&g_grad[3 * i + 1], -cf * dy);
        atomicAdd(&g_grad[3 * i + 2], -cf * dz);
    } else {
        int t = (blockIdx.x - nbr) * 128 + threadIdx.x;
        if (t >= T) return;
        int c = tri[t], a = tri[T + t], b = tri[2 * T + t];
        if (sgp[c] < 0) return;
        float v1x = crd[3 * a + 0] - crd[3 * c + 0];
        float v1y = crd[3 * a + 1] - crd[3 * c + 1];
        float v1z = crd[3 * a + 2] - crd[3 * c + 2];
        float v2x = crd[3 * b + 0] - crd[3 * c + 0];
        float v2y = crd[3 * b + 1] - crd[3 * c + 1];
        float v2z = crd[3 * b + 2] - crd[3 * c + 2];
        float d1 = sqrtf(v1x * v1x + v1y * v1y + v1z * v1z);
        float d2 = sqrtf(v2x * v2x + v2y * v2y + v2z * v2z);
        float id1 = 1.f / d1, id2 = 1.f / d2;
        float dot = v1x * v2x + v1y * v2y + v1z * v2z;
        float cosang = 0.95f * dot * id1 * id2;
        float ang = acosf(cosang);
        float fc1 = fcut(d1, 3.5f), fc2 = fcut(d2, 3.5f);
        float fc1p = dfcut(d1, 3.5f), fc2p = dfcut(d2, 3.5f);
        float fcj = fc1 * fc2;
        float u = 0.5f * (d1 + d2);

        float f1[4], df1[4];
#pragma unroll
        for (int z = 0; z < 4; z++) {
            float th = ang - ((float)z + 0.5f) * (PI_F / 4.f);
            float ct = cosf(th), st = sinf(th);
            float tt = 0.5f * (1.f + ct);
            float p13 = powf(tt, 13.1f);
            f1[z] = p13 * tt;
            df1[z] = 14.1f * p13 * (-0.5f * st);
        }
        float f2[8], df2[8];
#pragma unroll
        for (int s8 = 0; s8 < 8; s8++) {
            float dd = u - (0.8f + 0.3375f * (float)s8);
            f2[s8] = expf(-12.5f * dd * dd);
            df2[s8] = -25.f * dd * f2[s8];
        }
        int pidx = pair_index(sp[a], sp[b]);
        const float* g = g_gaev + (size_t)c * AEVD + 112 + pidx * 32;

        float Sg = 0.f, SdA = 0.f, Sdu = 0.f;
#pragma unroll
        for (int s8 = 0; s8 < 8; s8++) {
#pragma unroll
            for (int z = 0; z < 4; z++) {
                float gv = g[s8 * 4 + z];
                Sg  += gv * f2[s8] * f1[z];
                SdA += gv * f2[s8] * df1[z];
                Sdu += gv * df2[s8] * f1[z];
            }
        }
        float dLdA = 2.f * fcj * SdA;
        float dLdu = 2.f * fcj * Sdu;
        float dLdfc1 = 2.f * fc2 * Sg;
        float dLdfc2 = 2.f * fc1 * Sg;

        float dLdcos = dLdA * (-rsqrtf(fmaxf(1.f - cosang * cosang, 1e-12f)));
        float cA = 0.95f * id1 * id2;
        float cB1 = 0.95f * dot * id1 * id1 * id1 * id2;
        float cB2 = 0.95f * dot * id2 * id2 * id2 * id1;
        float r1 = (0.5f * dLdu + dLdfc1 * fc1p) * id1;
        float r2 = (0.5f * dLdu + dLdfc2 * fc2p) * id2;

        float g1x = dLdcos * (cA * v2x - cB1 * v1x) + r1 * v1x;
        float g1y = dLdcos * (cA * v2y - cB1 * v1y) + r1 * v1y;
        float g1z = dLdcos * (cA * v2z - cB1 * v1z) + r1 * v1z;
        float g2x = dLdcos * (cA * v1x - cB2 * v2x) + r2 * v2x;
        float g2y = dLdcos * (cA * v1y - cB2 * v2y) + r2 * v2y;
        float g2z = dLdcos * (cA * v1z - cB2 * v2z) + r2 * v2z;

        atomicAdd(&g_grad[3 * a + 0], g1x);
        atomicAdd(&g_grad[3 * a + 1], g1y);
        atomicAdd(&g_grad[3 * a + 2], g1z);
        atomicAdd(&g_grad[3 * b + 0], g2x);
        atomicAdd(&g_grad[3 * b + 1], g2y);
        atomicAdd(&g_grad[3 * b + 2], g2z);
        atomicAdd(&g_grad[3 * c + 0], -(g1x + g2x));
        atomicAdd(&g_grad[3 * c + 1], -(g1y + g2y));
        atomicAdd(&g_grad[3 * c + 2], -(g1z + g2z));
    }
}

// ---------------- finalize ----------------
__global__ void k_fin(float* __restrict__ out, int N, int out_size) {
    int i = blockIdx.x * blockDim.x + threadIdx.x;
    if (i >= out_size) return;
    if (i == 0) { out[0] = g_energy; return; }
    int k = i - 1;
    out[i] = (k < 3 * N) ? -g_grad[k] : 0.f;
}

// ---------------- host launcher ----------------
extern "C" void kernel_launch(void* const* d_in, const int* in_sizes, int n_in,
                              void* d_out, int out_size) {
    const int*   species = (const int*)d_in[0];
    const float* coords  = (const float*)d_in[1];
    const int*   idx12   = (const int*)d_in[2];
    const int*   tri     = (const int*)d_in[3];
    const int*   sgp     = (const int*)d_in[4];
    const float* W1 = (const float*)d_in[5];
    const float* b1 = (const float*)d_in[6];
    const float* W2 = (const float*)d_in[7];
    const float* b2 = (const float*)d_in[8];
    const float* W3 = (const float*)d_in[9];
    const float* b3 = (const float*)d_in[10];
    const float* W4 = (const float*)d_in[11];
    const float* b4 = (const float*)d_in[12];
    const float* sae = (const float*)d_in[13];
    int N = in_sizes[0];
    int P = in_sizes[2] / 2;
    int T = in_sizes[3] / 3;
    float* out = (float*)d_out;
    if (N > MAXN) return;

    float *p_aev, *p_gaev, *p_h1, *p_h2, *p_g1, *p_g2, *p_g3;
    cudaGetSymbolAddress((void**)&p_aev,  g_aev);
    cudaGetSymbolAddress((void**)&p_gaev, g_gaev);
    cudaGetSymbolAddress((void**)&p_h1,   g_h1);
    cudaGetSymbolAddress((void**)&p_h2,   g_h2);
    cudaGetSymbolAddress((void**)&p_g1,   g_g1);
    cudaGetSymbolAddress((void**)&p_g2,   g_g2);
    cudaGetSymbolAddress((void**)&p_g3,   g_g3);

    int nbr = (P + 127) / 128;
    int nba = (T + 127) / 128;

    k_zero<<<1024, 256>>>(N);
    k_prep<<<1, 1024>>>(sgp, sae, b4, N);
    k_aev_fwd<<<nbr + nba, 128>>>(coords, species, idx12, P, tri, T, nbr);

    // forward MLP (L3 fused with head via EPI=3)
    k_gemm<1008, 256, 1, false, false, false><<<dim3(4, MAXTILES, 8), 256>>>(p_aev, W1, b1, nullptr, p_h1, nullptr);
    k_gemm<256,  192, 1, false, true,  false><<<dim3(3, MAXTILES, 8), 256>>>(p_h1,  W2, b2, nullptr, p_h2, nullptr);
    k_gemm<192,  160, 3, false, true,  false><<<dim3(3, MAXTILES, 8), 256>>>(p_h2,  W3, b3, nullptr, p_g3, W4);
    // backward MLP
    k_gemm<160,  192, 2, true,  true,  false><<<dim3(3, MAXTILES, 8), 256>>>(p_g3, W3, nullptr, p_h2, p_g2, nullptr);
    k_gemm<192,  256, 2, true,  true,  false><<<dim3(4, MAXTILES, 8), 256>>>(p_g2, W2, nullptr, p_h1, p_g1, nullptr);
    k_gemm<256, 1008, 0, true,  true,  true ><<<dim3(16, MAXTILES, 1), 256>>>(p_g1, W1, nullptr, nullptr, p_gaev, nullptr);
    // AEV backward -> forces
    k_aev_bwd<<<nbr + nba, 128>>>(coords, species, sgp, idx12, P, tri, T, nbr);

    k_fin<<<(out_size + 255) / 256, 256>>>(out, N, out_size);
}